// round 11
// baseline (speedup 1.0000x reference)
#include <cuda_runtime.h>
#include <cuda_bf16.h>
#include <cstdint>

// Problem constants (fixed by setup_inputs)
#define NUM_NEW 50000
#define D_MODEL 3584
#define D_ENC   128
#define NB      2048      // batch / segments
#define SEG     32        // tokens per segment
#define CDIM    128       // dims per chunk (R11: one wide pass; D_MODEL = 28*128)
#define NCHUNK  28
#define G       32        // segments per block
#define NGRP    (NB / G)  // 64 groups

// ---------------------------------------------------------------------------
// Fully fused kernel: embedding gather + segment mean + projection.
// grid = (64 groups FAST, 28 chunks SLOW)  -- keeps R10's L2 dedup:
// co-resident CTAs share one chunk's ~18.7MB unique row-slice set in L2
// (DRAM traffic ~540MB, verified R10: DRAM 55%, 4.4TB/s).
//
// R11 vs R10 (125.3us, L1 60.8% = new wall):
//  - float4 gather (chunk=128 dims, lane*4): LDG instr count halved, bytes
//    in flight per outstanding load doubled -> higher DRAM duty.
//  - matvec re-tiled to (n-quad x 4-seg): per thread 256 LDS + 2048 FMA
//    (8:1, was 1.8:1) using LDS.128 for both Ws (contiguous) and means
//    (broadcast) -> smem crossbar cycles cut ~3x.
// ---------------------------------------------------------------------------
__global__ __launch_bounds__(256, 2) void fused_gather_proj_kernel(
    const int*   __restrict__ flat_idx,
    const int*   __restrict__ lens,
    const float* __restrict__ embed,
    const float* __restrict__ W,
    const float* __restrict__ bias,
    float*       __restrict__ out)
{
    __shared__ float Ws[CDIM][D_ENC];      // 64 KB
    __shared__ float means[G][CDIM];       // 16 KB
    __shared__ int   idx_s[G * SEG];       // 4 KB

    const int grp   = blockIdx.x;          // fast axis: groups (L2 dedup)
    const int chunk = blockIdx.y;          // slow axis: 128-dim chunks
    const int t     = threadIdx.x;
    const int w     = t >> 5;
    const int lane  = t & 31;

    // matvec mapping: warp-uniform 4-segment group, per-lane n-quad
    const int nq = lane;        // n = nq*4 .. nq*4+3
    const int sq = w;           // segments sq*4 .. sq*4+3

    // Stage token indices (1024) and the W slice [128][128]
    {
        const int base = grp * (G * SEG);
        #pragma unroll
        for (int i = 0; i < (G * SEG) / 256; i++)
            idx_s[t + i * 256] = flat_idx[base + t + i * 256];

        const float* Wc = W + (size_t)chunk * CDIM * D_ENC;
        float* Wd = &Ws[0][0];
        #pragma unroll
        for (int i = 0; i < (CDIM * D_ENC) / (256 * 4); i++) {  // 16 iters
            const int e = (t + i * 256) * 4;
            *reinterpret_cast<float4*>(Wd + e) =
                *reinterpret_cast<const float4*>(Wc + e);
        }
    }
    __syncthreads();

    // ---- Gather + mean: warp w handles segments w, w+8, w+16, w+24 ----
    // Each lane accumulates a float4 (512B coalesced per token row).
    {
        const int doff = chunk * CDIM + lane * 4;
        #pragma unroll 1
        for (int r = 0; r < 4; r++) {
            const int s = w + r * 8;
            float4 a = make_float4(0.f, 0.f, 0.f, 0.f);
            #pragma unroll
            for (int tok = 0; tok < SEG; tok++) {
                const int idx = idx_s[s * SEG + tok];
                const float4 v = __ldg(reinterpret_cast<const float4*>(
                    embed + (size_t)idx * D_MODEL + doff));
                a.x += v.x; a.y += v.y; a.z += v.z; a.w += v.w;
            }
            const float inv = 1.0f / (float)__ldg(&lens[grp * G + s]);
            a.x *= inv; a.y *= inv; a.z *= inv; a.w *= inv;
            *reinterpret_cast<float4*>(&means[s][lane * 4]) = a;
        }
    }
    __syncthreads();

    // ---- Matvec: acc[j][i] += means[sq*4+j][d] * Ws[d][nq*4+i] ----
    float acc[4][4];
    #pragma unroll
    for (int j = 0; j < 4; j++)
        #pragma unroll
        for (int i = 0; i < 4; i++) acc[j][i] = 0.f;

    #pragma unroll 4
    for (int d0 = 0; d0 < CDIM; d0 += 4) {
        float4 wv[4];
        #pragma unroll
        for (int dd = 0; dd < 4; dd++)
            wv[dd] = *reinterpret_cast<const float4*>(&Ws[d0 + dd][nq * 4]);
        #pragma unroll
        for (int j = 0; j < 4; j++) {
            const float4 m4 = *reinterpret_cast<const float4*>(
                &means[sq * 4 + j][d0]);  // warp-broadcast LDS.128
            acc[j][0] = fmaf(m4.x, wv[0].x, acc[j][0]);
            acc[j][1] = fmaf(m4.x, wv[0].y, acc[j][1]);
            acc[j][2] = fmaf(m4.x, wv[0].z, acc[j][2]);
            acc[j][3] = fmaf(m4.x, wv[0].w, acc[j][3]);
            acc[j][0] = fmaf(m4.y, wv[1].x, acc[j][0]);
            acc[j][1] = fmaf(m4.y, wv[1].y, acc[j][1]);
            acc[j][2] = fmaf(m4.y, wv[1].z, acc[j][2]);
            acc[j][3] = fmaf(m4.y, wv[1].w, acc[j][3]);
            acc[j][0] = fmaf(m4.z, wv[2].x, acc[j][0]);
            acc[j][1] = fmaf(m4.z, wv[2].y, acc[j][1]);
            acc[j][2] = fmaf(m4.z, wv[2].z, acc[j][2]);
            acc[j][3] = fmaf(m4.z, wv[2].w, acc[j][3]);
            acc[j][0] = fmaf(m4.w, wv[3].x, acc[j][0]);
            acc[j][1] = fmaf(m4.w, wv[3].y, acc[j][1]);
            acc[j][2] = fmaf(m4.w, wv[3].z, acc[j][2]);
            acc[j][3] = fmaf(m4.w, wv[3].w, acc[j][3]);
        }
    }

    // ---- Epilogue: atomic accumulate (+bias from chunk 0) ----
    const bool add_bias = (chunk == 0);
    const int  n = nq * 4;
    float b[4] = {0.f, 0.f, 0.f, 0.f};
    if (add_bias) {
        const float4 bv = *reinterpret_cast<const float4*>(&bias[n]);
        b[0] = bv.x; b[1] = bv.y; b[2] = bv.z; b[3] = bv.w;
    }
    #pragma unroll
    for (int j = 0; j < 4; j++) {
        const int s = grp * G + sq * 4 + j;
        #pragma unroll
        for (int i = 0; i < 4; i++)
            atomicAdd(&out[(size_t)s * D_ENC + n + i], acc[j][i] + b[i]);
    }
}

// ---------------------------------------------------------------------------
// Launch.  Inputs (metadata order):
//   0: flat_idx int32 [65536]   1: seg int32 [65536]   2: lens int32 [2048]
//   3: embed_weight f32 [50000*3584]  4: proj_w f32 [3584*128]  5: proj_b f32 [128]
// Output: f32 [2048*128]
// ---------------------------------------------------------------------------
extern "C" void kernel_launch(void* const* d_in, const int* in_sizes, int n_in,
                              void* d_out, int out_size)
{
    const int*   flat_idx = (const int*)d_in[0];
    const int*   lens     = (const int*)d_in[2];
    const float* embed    = (const float*)d_in[3];
    const float* proj_w   = (const float*)d_in[4];
    const float* proj_b   = (const float*)d_in[5];
    float*       out      = (float*)d_out;

    // zero output (atomics accumulate; bias added by chunk 0)
    cudaMemsetAsync(out, 0, (size_t)NB * D_ENC * sizeof(float));

    // grid: groups fast (L2 dedup), chunks slow
    fused_gather_proj_kernel<<<dim3(NGRP, NCHUNK), 256>>>(
        flat_idx, lens, embed, proj_w, proj_b, out);
}

// round 13
// speedup vs baseline: 1.2351x; 1.2351x over previous
#include <cuda_runtime.h>
#include <cuda_bf16.h>
#include <cstdint>

// Problem constants (fixed by setup_inputs)
#define NUM_NEW 50000
#define D_MODEL 3584
#define D_ENC   128
#define NB      2048      // batch / segments
#define SEG     32        // tokens per segment
#define CDIM    64        // dims per chunk pass (R10 geometry: best gather)
#define NCP     28        // chunk-pairs (block covers 2 chunks)
#define G       32        // segments per block
#define NGRP    (NB / G)  // 64 groups
#define KW      32        // k-words per chunk (64 dims -> 32 bf16x2 words)
#define SW      36        // smem row stride in words (frag banks (4lq+ls)%32: conflict-free)

// ---------------------------------------------------------------------------
// Fully fused kernel: embedding gather + segment mean + tensor-core projection.
// grid = (64 groups FAST, 28 chunk-pairs SLOW) -- keeps R10's L2 dedup
// (~36.5K unique rows/chunk -> 18.7MB L2-resident, DRAM ~540MB).
//
// R12 vs R10 (125.3us): the SIMT matvec (576 LDS + 1024 FMA per thread per
// chunk, ~40% of CTA time with zero loads in flight) is replaced by
// mma.sync.m16n8k16 bf16 with hi/lo split (R6-proven): per WARP per chunk
// only 96 LDS + 48 mma. Gather emits means as packed bf16 h/l directly.
// CTA time becomes ~90% gather -> DRAM/L2 duty up.
// ---------------------------------------------------------------------------

__device__ __forceinline__ void split2(float x, float y, uint32_t& h, uint32_t& l) {
    __nv_bfloat16 hx = __float2bfloat16(x);
    __nv_bfloat16 hy = __float2bfloat16(y);
    __nv_bfloat16 lx = __float2bfloat16(x - __bfloat162float(hx));
    __nv_bfloat16 ly = __float2bfloat16(y - __bfloat162float(hy));
    h = ((uint32_t)__bfloat16_as_ushort(hy) << 16) | __bfloat16_as_ushort(hx);
    l = ((uint32_t)__bfloat16_as_ushort(ly) << 16) | __bfloat16_as_ushort(lx);
}

__device__ __forceinline__ void mma16(float* d, const uint32_t* a, const uint32_t* b) {
    asm volatile(
        "mma.sync.aligned.m16n8k16.row.col.f32.bf16.bf16.f32 "
        "{%0,%1,%2,%3}, {%4,%5,%6,%7}, {%8,%9}, {%0,%1,%2,%3};\n"
        : "+f"(d[0]), "+f"(d[1]), "+f"(d[2]), "+f"(d[3])
        : "r"(a[0]), "r"(a[1]), "r"(a[2]), "r"(a[3]), "r"(b[0]), "r"(b[1]));
}

__global__ __launch_bounds__(256, 2) void fused_gather_proj_kernel(
    const int*   __restrict__ flat_idx,
    const int*   __restrict__ lens,
    const float* __restrict__ embed,
    const float* __restrict__ W,
    const float* __restrict__ bias,
    float*       __restrict__ out)
{
    __shared__ uint32_t Bh[D_ENC][SW];   // W slice, n-major k-words, hi  (18.4 KB)
    __shared__ uint32_t Bl[D_ENC][SW];   //                           lo  (18.4 KB)
    __shared__ uint32_t Mh[G][SW];       // means hi (4.6 KB)
    __shared__ uint32_t Ml[G][SW];       // means lo (4.6 KB)
    __shared__ int      idx_s[G * SEG];  // 4 KB

    const int grp   = blockIdx.x;        // fast axis: groups (L2 dedup)
    const int cpair = blockIdx.y;        // slow axis: chunk-pairs
    const int t     = threadIdx.x;
    const int w     = t >> 5;
    const int lane  = t & 31;
    const int lq    = lane >> 2;         // 0..7
    const int ls    = lane & 3;          // 0..3

    // mma warp tiling of C=[32 segs][128 n]: 2(m) x 4(n) warps -> 16x32 per warp
    const int wm = (w & 1) * 16;
    const int wn = (w >> 1) * 32;

    // Stage token indices (1024, contiguous)
    {
        const int base = grp * (G * SEG);
        #pragma unroll
        for (int i = 0; i < (G * SEG) / 256; i++)
            idx_s[t + i * 256] = flat_idx[base + t + i * 256];
    }

    float acc[4][4];   // [n-tile][c-frag], accumulates across both chunks
    #pragma unroll
    for (int nt = 0; nt < 4; nt++)
        #pragma unroll
        for (int r = 0; r < 4; r++) acc[nt][r] = 0.f;

    #pragma unroll 1
    for (int cp = 0; cp < 2; cp++) {
        const int chunk = cpair * 2 + cp;

        __syncthreads();  // cp0: idx ready; cp1: previous mma done reading

        // Stage W slice with transpose + bf16 h/l split:
        // Bh/Bl[n][kw] = pack(W[d][n], W[d+1][n]), d = chunk*64 + 2*kw.
        // Lanes sweep n (coalesced 128B LDG), kw fixed per iteration wave.
        {
            const float* Wc = W + (size_t)chunk * CDIM * D_ENC;
            #pragma unroll
            for (int i = 0; i < (CDIM / 2 * D_ENC) / 256; i++) {  // 16 iters
                const int wordid = t + i * 256;
                const int n  = wordid & 127;
                const int kw = wordid >> 7;
                const float w0 = __ldg(Wc + (size_t)(2 * kw)     * D_ENC + n);
                const float w1 = __ldg(Wc + (size_t)(2 * kw + 1) * D_ENC + n);
                uint32_t h, l;
                split2(w0, w1, h, l);
                Bh[n][kw] = h;
                Bl[n][kw] = l;
            }
        }

        // Gather + mean (R10 geometry): warp w -> segments w, w+8, w+16, w+24;
        // lane owns dim-pair (lane*2) -> one packed word per segment.
        {
            const int doff = chunk * CDIM + lane * 2;
            #pragma unroll 1
            for (int r = 0; r < 4; r++) {
                const int s = w + r * 8;
                float ax = 0.f, ay = 0.f;
                #pragma unroll
                for (int tok = 0; tok < SEG; tok++) {
                    const int idx = idx_s[s * SEG + tok];
                    const float2 v = __ldg(reinterpret_cast<const float2*>(
                        embed + (size_t)idx * D_MODEL + doff));
                    ax += v.x; ay += v.y;
                }
                const float inv = 1.0f / (float)__ldg(&lens[grp * G + s]);
                uint32_t h, l;
                split2(ax * inv, ay * inv, h, l);
                Mh[s][lane] = h;
                Ml[s][lane] = l;
            }
        }
        __syncthreads();  // Bs + means ready

        // Tensor-core matvec: C += means @ Wslice  (hi*hi + hi*lo + lo*hi)
        // 4 k16-steps (64 dims); per warp: 96 LDS + 48 mma total.
        #pragma unroll
        for (int ks = 0; ks < 4; ks++) {
            const int kw0 = ks * 8;
            uint32_t ah[4], al[4];
            ah[0] = Mh[wm + lq    ][kw0 + ls];
            ah[1] = Mh[wm + lq + 8][kw0 + ls];
            ah[2] = Mh[wm + lq    ][kw0 + ls + 4];
            ah[3] = Mh[wm + lq + 8][kw0 + ls + 4];
            al[0] = Ml[wm + lq    ][kw0 + ls];
            al[1] = Ml[wm + lq + 8][kw0 + ls];
            al[2] = Ml[wm + lq    ][kw0 + ls + 4];
            al[3] = Ml[wm + lq + 8][kw0 + ls + 4];
            #pragma unroll
            for (int nt = 0; nt < 4; nt++) {
                const int col = wn + nt * 8 + lq;
                uint32_t bh[2], bl[2];
                bh[0] = Bh[col][kw0 + ls];
                bh[1] = Bh[col][kw0 + ls + 4];
                bl[0] = Bl[col][kw0 + ls];
                bl[1] = Bl[col][kw0 + ls + 4];
                mma16(acc[nt], ah, bh);  // hi*hi
                mma16(acc[nt], ah, bl);  // hi*lo
                mma16(acc[nt], al, bh);  // lo*hi  (lo*lo ~2^-32: dropped)
            }
        }
    }

    // Epilogue: atomic accumulate (28 chunk-pair contributions per element).
    // cpair 0 adds the bias. C frag: rows wm+lq / wm+lq+8, cols 2ls / 2ls+1.
    const bool add_bias = (cpair == 0);
    #pragma unroll
    for (int nt = 0; nt < 4; nt++) {
        const int n = wn + nt * 8 + ls * 2;
        float v0 = acc[nt][0], v1 = acc[nt][1];
        float v2 = acc[nt][2], v3 = acc[nt][3];
        if (add_bias) {
            const float b0 = bias[n], b1 = bias[n + 1];
            v0 += b0; v1 += b1; v2 += b0; v3 += b1;
        }
        const int s0 = grp * G + wm + lq;
        atomicAdd(&out[(size_t)s0 * D_ENC + n],           v0);
        atomicAdd(&out[(size_t)s0 * D_ENC + n + 1],       v1);
        atomicAdd(&out[(size_t)(s0 + 8) * D_ENC + n],     v2);
        atomicAdd(&out[(size_t)(s0 + 8) * D_ENC + n + 1], v3);
    }
}

// ---------------------------------------------------------------------------
// Launch.  Inputs (metadata order):
//   0: flat_idx int32 [65536]   1: seg int32 [65536]   2: lens int32 [2048]
//   3: embed_weight f32 [50000*3584]  4: proj_w f32 [3584*128]  5: proj_b f32 [128]
// Output: f32 [2048*128]
// ---------------------------------------------------------------------------
extern "C" void kernel_launch(void* const* d_in, const int* in_sizes, int n_in,
                              void* d_out, int out_size)
{
    const int*   flat_idx = (const int*)d_in[0];
    const int*   lens     = (const int*)d_in[2];
    const float* embed    = (const float*)d_in[3];
    const float* proj_w   = (const float*)d_in[4];
    const float* proj_b   = (const float*)d_in[5];
    float*       out      = (float*)d_out;

    // zero output (atomics accumulate; bias added by chunk-pair 0)
    cudaMemsetAsync(out, 0, (size_t)NB * D_ENC * sizeof(float));

    // grid: groups fast (L2 dedup), chunk-pairs slow
    fused_gather_proj_kernel<<<dim3(NGRP, NCP), 256>>>(
        flat_idx, lens, embed, proj_w, proj_b, out);
}

// round 14
// speedup vs baseline: 1.4722x; 1.1919x over previous
#include <cuda_runtime.h>
#include <cuda_bf16.h>
#include <cstdint>

// Problem constants (fixed by setup_inputs)
#define NUM_NEW 50000
#define D_MODEL 3584
#define D_ENC   128
#define NB      2048      // batch / segments
#define SEG     32        // tokens per segment
#define CDIM    64        // dims per chunk pass
#define NCP     28        // chunk-pairs (block covers 2 chunks)
#define NCHUNK  56
#define G       32        // segments per block
#define NGRP    (NB / G)  // 64 groups
#define KW      32        // bf16x2 k-words per chunk (64 dims)
#define SW      36        // smem row stride in words (frag banks conflict-free)

// Prepacked W: chunk-blocked, n-major: g_B{h,l}[chunk][n][kw]  (458 KB each)
__device__ uint32_t g_Bh[NCHUNK * D_ENC * KW];
__device__ uint32_t g_Bl[NCHUNK * D_ENC * KW];

__device__ __forceinline__ void split2(float x, float y, uint32_t& h, uint32_t& l) {
    __nv_bfloat16 hx = __float2bfloat16(x);
    __nv_bfloat16 hy = __float2bfloat16(y);
    __nv_bfloat16 lx = __float2bfloat16(x - __bfloat162float(hx));
    __nv_bfloat16 ly = __float2bfloat16(y - __bfloat162float(hy));
    h = ((uint32_t)__bfloat16_as_ushort(hy) << 16) | __bfloat16_as_ushort(hx);
    l = ((uint32_t)__bfloat16_as_ushort(ly) << 16) | __bfloat16_as_ushort(lx);
}

__device__ __forceinline__ void mma16(float* d, const uint32_t* a, const uint32_t* b) {
    asm volatile(
        "mma.sync.aligned.m16n8k16.row.col.f32.bf16.bf16.f32 "
        "{%0,%1,%2,%3}, {%4,%5,%6,%7}, {%8,%9}, {%0,%1,%2,%3};\n"
        : "+f"(d[0]), "+f"(d[1]), "+f"(d[2]), "+f"(d[3])
        : "r"(a[0]), "r"(a[1]), "r"(a[2]), "r"(a[3]), "r"(b[0]), "r"(b[1]));
}

// ---------------------------------------------------------------------------
// Prepack kernel (~5us, once per launch): W [3584][128] -> chunk-blocked
// bf16 hi/lo words. word (chunk, n, kw) packs W[chunk*64+2kw][n], W[..+1][n].
// Reads coalesced over n (tid fastest), strided stores (tiny volume).
// ---------------------------------------------------------------------------
__global__ __launch_bounds__(256) void prepack_w_kernel(const float* __restrict__ W) {
    const int tid = blockIdx.x * 256 + threadIdx.x;   // over n fastest
    if (tid >= NCHUNK * KW * D_ENC) return;
    const int n     = tid & 127;
    const int kw    = (tid >> 7) & 31;
    const int chunk = tid >> 12;
    const int d     = chunk * CDIM + 2 * kw;
    const float w0 = __ldg(W + (size_t)d * D_ENC + n);
    const float w1 = __ldg(W + (size_t)(d + 1) * D_ENC + n);
    uint32_t h, l;
    split2(w0, w1, h, l);
    const int dst = (chunk * D_ENC + n) * KW + kw;
    g_Bh[dst] = h;
    g_Bl[dst] = l;
}

// ---------------------------------------------------------------------------
// Fully fused kernel: gather + segment mean + tensor-core projection.
// grid = (64 groups FAST, 28 chunk-pairs SLOW) -- R10 L2 dedup preserved.
//
// R14 vs R13 (137.3us): W staging is now 8 coalesced uint4 copies/thread
// (prepacked globals, L2-resident) instead of 32 scalar LDG + 16 split2
// -> matvec phase ~5% of CTA time; gather identical to R10's best.
// ---------------------------------------------------------------------------
__global__ __launch_bounds__(256, 2) void fused_gather_proj_kernel(
    const int*   __restrict__ flat_idx,
    const int*   __restrict__ lens,
    const float* __restrict__ embed,
    const float* __restrict__ bias,
    float*       __restrict__ out)
{
    __shared__ uint32_t Bh[D_ENC][SW];   // 18.4 KB
    __shared__ uint32_t Bl[D_ENC][SW];   // 18.4 KB
    __shared__ uint32_t Mh[G][SW];       // 4.6 KB
    __shared__ uint32_t Ml[G][SW];       // 4.6 KB
    __shared__ int      idx_s[G * SEG];  // 4 KB

    const int grp   = blockIdx.x;        // fast axis: groups (L2 dedup)
    const int cpair = blockIdx.y;
    const int t     = threadIdx.x;
    const int w     = t >> 5;
    const int lane  = t & 31;
    const int lq    = lane >> 2;
    const int ls    = lane & 3;

    // mma warp tiling of C=[32 segs][128 n]: 2(m) x 4(n) warps
    const int wm = (w & 1) * 16;
    const int wn = (w >> 1) * 32;

    // Stage token indices (1024, contiguous)
    {
        const int base = grp * (G * SEG);
        #pragma unroll
        for (int i = 0; i < (G * SEG) / 256; i++)
            idx_s[t + i * 256] = flat_idx[base + t + i * 256];
    }

    float acc[4][4];
    #pragma unroll
    for (int nt = 0; nt < 4; nt++)
        #pragma unroll
        for (int r = 0; r < 4; r++) acc[nt][r] = 0.f;

    #pragma unroll 1
    for (int cp = 0; cp < 2; cp++) {
        const int chunk = cpair * 2 + cp;

        __syncthreads();  // cp0: idx ready; cp1: previous mma done reading

        // Stage prepacked W slice: 1024 uint4 per array, 4 per thread.
        {
            const uint32_t* srcH = g_Bh + (size_t)chunk * D_ENC * KW;
            const uint32_t* srcL = g_Bl + (size_t)chunk * D_ENC * KW;
            #pragma unroll
            for (int i = 0; i < 4; i++) {
                const int widx = t + i * 256;       // uint4 index
                const int n    = widx >> 3;         // 8 uint4 per n-row
                const int kw   = (widx & 7) * 4;
                *reinterpret_cast<uint4*>(&Bh[n][kw]) =
                    *reinterpret_cast<const uint4*>(srcH + widx * 4);
                *reinterpret_cast<uint4*>(&Bl[n][kw]) =
                    *reinterpret_cast<const uint4*>(srcL + widx * 4);
            }
        }

        // Gather + mean (R10 geometry): warp w -> segments w, w+8, w+16, w+24;
        // lane owns dim-pair (lane*2), emits packed bf16 h/l words.
        {
            const int doff = chunk * CDIM + lane * 2;
            #pragma unroll 1
            for (int r = 0; r < 4; r++) {
                const int s = w + r * 8;
                float ax = 0.f, ay = 0.f;
                #pragma unroll
                for (int tok = 0; tok < SEG; tok++) {
                    const int idx = idx_s[s * SEG + tok];
                    const float2 v = __ldg(reinterpret_cast<const float2*>(
                        embed + (size_t)idx * D_MODEL + doff));
                    ax += v.x; ay += v.y;
                }
                const float inv = 1.0f / (float)__ldg(&lens[grp * G + s]);
                uint32_t h, l;
                split2(ax * inv, ay * inv, h, l);
                Mh[s][lane] = h;
                Ml[s][lane] = l;
            }
        }
        __syncthreads();  // Bs + means ready

        // Tensor-core matvec: C += means @ Wslice (hi*hi + hi*lo + lo*hi)
        #pragma unroll
        for (int ks = 0; ks < 4; ks++) {
            const int kw0 = ks * 8;
            uint32_t ah[4], al[4];
            ah[0] = Mh[wm + lq    ][kw0 + ls];
            ah[1] = Mh[wm + lq + 8][kw0 + ls];
            ah[2] = Mh[wm + lq    ][kw0 + ls + 4];
            ah[3] = Mh[wm + lq + 8][kw0 + ls + 4];
            al[0] = Ml[wm + lq    ][kw0 + ls];
            al[1] = Ml[wm + lq + 8][kw0 + ls];
            al[2] = Ml[wm + lq    ][kw0 + ls + 4];
            al[3] = Ml[wm + lq + 8][kw0 + ls + 4];
            #pragma unroll
            for (int nt = 0; nt < 4; nt++) {
                const int col = wn + nt * 8 + lq;
                uint32_t bh[2], bl[2];
                bh[0] = Bh[col][kw0 + ls];
                bh[1] = Bh[col][kw0 + ls + 4];
                bl[0] = Bl[col][kw0 + ls];
                bl[1] = Bl[col][kw0 + ls + 4];
                mma16(acc[nt], ah, bh);  // hi*hi
                mma16(acc[nt], ah, bl);  // hi*lo
                mma16(acc[nt], al, bh);  // lo*hi
            }
        }
    }

    // Epilogue: atomic accumulate; cpair 0 adds bias.
    const bool add_bias = (cpair == 0);
    #pragma unroll
    for (int nt = 0; nt < 4; nt++) {
        const int n = wn + nt * 8 + ls * 2;
        float v0 = acc[nt][0], v1 = acc[nt][1];
        float v2 = acc[nt][2], v3 = acc[nt][3];
        if (add_bias) {
            const float b0 = bias[n], b1 = bias[n + 1];
            v0 += b0; v1 += b1; v2 += b0; v3 += b1;
        }
        const int s0 = grp * G + wm + lq;
        atomicAdd(&out[(size_t)s0 * D_ENC + n],           v0);
        atomicAdd(&out[(size_t)s0 * D_ENC + n + 1],       v1);
        atomicAdd(&out[(size_t)(s0 + 8) * D_ENC + n],     v2);
        atomicAdd(&out[(size_t)(s0 + 8) * D_ENC + n + 1], v3);
    }
}

// ---------------------------------------------------------------------------
// Launch.  Inputs (metadata order):
//   0: flat_idx int32 [65536]   1: seg int32 [65536]   2: lens int32 [2048]
//   3: embed_weight f32 [50000*3584]  4: proj_w f32 [3584*128]  5: proj_b f32 [128]
// Output: f32 [2048*128]
// ---------------------------------------------------------------------------
extern "C" void kernel_launch(void* const* d_in, const int* in_sizes, int n_in,
                              void* d_out, int out_size)
{
    const int*   flat_idx = (const int*)d_in[0];
    const int*   lens     = (const int*)d_in[2];
    const float* embed    = (const float*)d_in[3];
    const float* proj_w   = (const float*)d_in[4];
    const float* proj_b   = (const float*)d_in[5];
    float*       out      = (float*)d_out;

    // zero output (atomics accumulate; bias added by chunk-pair 0)
    cudaMemsetAsync(out, 0, (size_t)NB * D_ENC * sizeof(float));

    // prepack W into chunk-blocked bf16 hi/lo (same stream: ordered)
    prepack_w_kernel<<<(NCHUNK * KW * D_ENC + 255) / 256, 256>>>(proj_w);

    // fused gather + mean + tensor-core projection
    fused_gather_proj_kernel<<<dim3(NGRP, NCP), 256>>>(
        flat_idx, lens, embed, proj_b, out);
}